// round 1
// baseline (speedup 1.0000x reference)
#include <cuda_runtime.h>

// AvgSeq: out[b,s,d] = cumsum_s(x[b,s,d]) / (s+1)
// Shapes fixed by the problem: B=16, S=8192, D=256, fp32.

#define B 16
#define S 8192
#define D 256
#define NC 64            // number of seq chunks
#define CLEN (S / NC)    // 128 seq elements per chunk

// Scratch: per-(b, chunk, d) partial sums. 16*64*256 floats = 4 MB.
__device__ float g_partial[B * NC * D];

// Pass 1: each thread (one per d) sums its chunk of CLEN seq steps.
// Loads fully coalesced: 256 threads x 4B = 1024B contiguous per step.
__global__ void __launch_bounds__(D) pass1_chunk_sums(const float* __restrict__ x) {
    const int d = threadIdx.x;
    const int c = blockIdx.x;
    const int b = blockIdx.y;
    const float* p = x + ((size_t)b * S + (size_t)c * CLEN) * D + d;
    float sum = 0.f;
#pragma unroll 8
    for (int s = 0; s < CLEN; ++s) {
        sum += p[(size_t)s * D];
    }
    g_partial[(b * NC + c) * D + d] = sum;
}

// Pass 2: exclusive scan over the NC chunk sums for each (b, d) lane.
// 16 blocks x 256 threads; trivial cost.
__global__ void __launch_bounds__(D) pass2_scan_sums() {
    const int d = threadIdx.x;
    const int b = blockIdx.x;
    float run = 0.f;
#pragma unroll 8
    for (int c = 0; c < NC; ++c) {
        const int idx = (b * NC + c) * D + d;
        const float v = g_partial[idx];
        g_partial[idx] = run;   // exclusive prefix
        run += v;
    }
}

// Pass 3: re-read input, local inclusive scan + offset, divide by (s+1).
__global__ void __launch_bounds__(D) pass3_scan_out(const float* __restrict__ x,
                                                    float* __restrict__ y) {
    const int d = threadIdx.x;
    const int c = blockIdx.x;
    const int b = blockIdx.y;
    float run = g_partial[(b * NC + c) * D + d];
    const size_t base = ((size_t)b * S + (size_t)c * CLEN) * D + d;
    const float* p = x + base;
    float* q = y + base;
    const int s0 = c * CLEN;
#pragma unroll 4
    for (int s = 0; s < CLEN; ++s) {
        run += p[(size_t)s * D];
        q[(size_t)s * D] = run / (float)(s0 + s + 1);
    }
}

extern "C" void kernel_launch(void* const* d_in, const int* in_sizes, int n_in,
                              void* d_out, int out_size) {
    const float* x = (const float*)d_in[0];
    float* y = (float*)d_out;

    dim3 grid1(NC, B);
    pass1_chunk_sums<<<grid1, D>>>(x);
    pass2_scan_sums<<<B, D>>>();
    pass3_scan_out<<<grid1, D>>>(x, y);
}